// round 7
// baseline (speedup 1.0000x reference)
#include <cuda_runtime.h>
#include <cstdint>

#define D      64
#define NROWS  8192
#define BM     128
#define BN     256
#define GAMMA  0.015625f
#define TWOG   0.03125f

// ---------------- device scratch: fragment-layout tf32 inputs ----------------
// A: g_Af[group(r>>4)][chunk(k>>3)][lane((r&7)*4+(k&3))][word(((k>>2)&1)*2+((r>>3)&1))]
// B: g_Bf[group(8 cols)][chunk(k>>4)][lane(gID*4+(k&3))][word((k>>2)&3)] (col-permuted)
__device__ float g_xs[NROWS];
__device__ float g_ys[NROWS];
__device__ float g_Af[NROWS * D];
__device__ float g_Bf[NROWS * D];

// ---------------- prep: tf32 round + fragment scatter + norms ----------------
__device__ __forceinline__ uint32_t tf32_of(float f) {
    uint32_t t;
    asm("cvt.rna.tf32.f32 %0, %1;" : "=r"(t) : "f"(f));
    return t;
}
__device__ __forceinline__ int idxA(int r, int k) {
    int grp  = r >> 4;
    int chnk = k >> 3;
    int lane = (r & 7) * 4 + (k & 3);
    int word = ((k >> 2) & 1) * 2 + ((r >> 3) & 1);
    return ((grp * 8 + chnk) * 32 + lane) * 4 + word;
}
__device__ __forceinline__ int idxB(int j, int k) {
    int w   = j & 15;                                       // within 16-col block
    int p   = 2 * (w >> 2) + (w & 1) + 8 * ((w >> 1) & 1);  // inverse perm16
    int grp = (j >> 4) * 2 + (p >> 3);
    int gID = p & 7;
    int lane = gID * 4 + (k & 3);
    int chnk = (k >> 4) & 3;
    int word = (k >> 2) & 3;
    return ((grp * 4 + chnk) * 32 + lane) * 4 + word;
}

__global__ void __launch_bounds__(256)
prep_kernel(const float* __restrict__ A, const float* __restrict__ B,
            int rows_each) {
    int half = gridDim.x >> 1;
    int bid  = blockIdx.x;
    bool isB = bid >= half;
    if (isB) bid -= half;

    int w    = bid * 8 + (threadIdx.x >> 5);
    int lane = threadIdx.x & 31;
    if (w >= rows_each) return;
    const float* r = (isB ? B : A) + (size_t)w * D;
    float f0 = r[lane];
    float f1 = r[lane + 32];

    if (!isB) {
        g_Af[idxA(w, lane)]      = __uint_as_float(tf32_of(f0));
        g_Af[idxA(w, lane + 32)] = __uint_as_float(tf32_of(f1));
    } else {
        g_Bf[idxB(w, lane)]      = __uint_as_float(tf32_of(f0));
        g_Bf[idxB(w, lane + 32)] = __uint_as_float(tf32_of(f1));
    }

    float s = f0 * f0 + f1 * f1;   // norms from exact f32
#pragma unroll
    for (int o = 16; o; o >>= 1) s += __shfl_xor_sync(0xffffffffu, s, o);
    if (lane == 0) (isB ? g_ys : g_xs)[w] = -GAMMA * s;
}

// ---------------- tf32 mma helper ----------------
__device__ __forceinline__ void mma_tf32(float* d, const uint32_t* a,
                                         const uint32_t* b) {
    asm volatile(
        "mma.sync.aligned.m16n8k8.row.col.f32.tf32.tf32.f32 "
        "{%0,%1,%2,%3}, {%4,%5,%6,%7}, {%8,%9}, {%0,%1,%2,%3};"
        : "+f"(d[0]), "+f"(d[1]), "+f"(d[2]), "+f"(d[3])
        : "r"(a[0]), "r"(a[1]), "r"(a[2]), "r"(a[3]), "r"(b[0]), "r"(b[1]));
}

// ---------------- main: smem-free tf32 HMMA, 64x64 warp tile --------------
__global__ void __launch_bounds__(256, 1)
rbf_tf32_kernel(float* __restrict__ out, int N) {
    const int tid  = threadIdx.x;
    const int lane = tid & 31;
    const int wid  = tid >> 5;
    const int gID  = lane >> 2;
    const int tig  = lane & 3;
    const int wm   = wid >> 2;    // 0..1 : 64-row slab
    const int wn   = wid & 3;     // 0..3 : 64-col slab
    const int row0 = blockIdx.y * BM;
    const int col0 = blockIdx.x * BN;

    const uint4* Af = reinterpret_cast<const uint4*>(g_Af);
    const uint4* Bf = reinterpret_cast<const uint4*>(g_Bf);

    // ---- hoist ALL B fragments for this warp's 64-col slab (32 LDG.128) ----
    uint4 bf[32];   // [group(8 cols)][chunk(16 k)]
    {
        const int bgrp0 = (col0 >> 3) + wn * 8;
#pragma unroll
        for (int g = 0; g < 8; g++)
#pragma unroll
            for (int c = 0; c < 4; c++)
                bf[g * 4 + c] = Bf[(size_t)(((bgrp0 + g) * 4 + c) * 32 + lane)];
    }
    const uint32_t* bw = reinterpret_cast<const uint32_t*>(bf);

#pragma unroll
    for (int mt = 0; mt < 4; mt++) {
        // A fragments for this 16-row group (8 LDG.128)
        uint4 af[8];
        const int agrp = (row0 >> 4) + wm * 4 + mt;
#pragma unroll
        for (int c = 0; c < 8; c++)
            af[c] = Af[(size_t)((agrp * 8 + c) * 32 + lane)];
        const uint32_t* aw = reinterpret_cast<const uint32_t*>(af);

        const int rbase = row0 + wm * 64 + mt * 16 + gID;
        const float xs0 = g_xs[rbase];
        const float xs1 = g_xs[rbase + 8];

#pragma unroll
        for (int pr = 0; pr < 4; pr++) {
            float accE[4] = {0.f, 0.f, 0.f, 0.f};
            float accO[4] = {0.f, 0.f, 0.f, 0.f};
#pragma unroll
            for (int ks = 0; ks < 8; ks++) {
                const uint32_t* a = aw + ks * 4;
                const uint32_t* bE =
                    bw + ((2 * pr) * 4 + (ks >> 1)) * 4 + (ks & 1) * 2;
                const uint32_t* bO =
                    bw + ((2 * pr + 1) * 4 + (ks >> 1)) * 4 + (ks & 1) * 2;
                mma_tf32(accE, a, bE);
                mma_tf32(accO, a, bO);
            }
            const int c = col0 + wn * 64 + pr * 16 + 4 * tig;
            const float4 ys4 = *reinterpret_cast<const float4*>(&g_ys[c]);
            float4 v0, v1;
            v0.x = __expf(fminf(xs0 + ys4.x + TWOG * accE[0], 0.f));
            v0.y = __expf(fminf(xs0 + ys4.y + TWOG * accE[1], 0.f));
            v0.z = __expf(fminf(xs0 + ys4.z + TWOG * accO[0], 0.f));
            v0.w = __expf(fminf(xs0 + ys4.w + TWOG * accO[1], 0.f));
            v1.x = __expf(fminf(xs1 + ys4.x + TWOG * accE[2], 0.f));
            v1.y = __expf(fminf(xs1 + ys4.y + TWOG * accE[3], 0.f));
            v1.z = __expf(fminf(xs1 + ys4.z + TWOG * accO[2], 0.f));
            v1.w = __expf(fminf(xs1 + ys4.w + TWOG * accO[3], 0.f));
            __stcs(reinterpret_cast<float4*>(out + (size_t)rbase * N + c), v0);
            __stcs(reinterpret_cast<float4*>(out + (size_t)(rbase + 8) * N + c), v1);
        }
    }
}

// ---------------------------------------------------------------------------
extern "C" void kernel_launch(void* const* d_in, const int* in_sizes, int n_in,
                              void* d_out, int out_size) {
    const float* A = (const float*)d_in[0];  // data        [M, 64]
    const float* B = (const float*)d_in[1];  // support_vec [N, 64]
    float* out     = (float*)d_out;          // [M, N]

    const int M = in_sizes[0] / D;           // 8192
    const int N = in_sizes[1] / D;           // 8192

    prep_kernel<<<(M + 7) / 8 * 2, 256>>>(A, B, M);

    dim3 grid(N / BN, M / BM);
    rbf_tf32_kernel<<<grid, 256>>>(out, N);
}

// round 8
// speedup vs baseline: 1.6164x; 1.6164x over previous
#include <cuda_runtime.h>
#include <cuda_fp16.h>
#include <cstdint>

#define D      64
#define NROWS  8192
#define BM     128
#define BN     256
#define GAMMA  0.015625f
#define TWOG   0.03125f

// ---------------- device scratch: fp16 fragment-layout inputs ----------------
// A (m16n8k16): value(r,k) -> grp=r>>4, chunk=k>>4, lane=(r&7)*4+((k&7)>>1),
//               reg=((r>>3)&1)+2*((k>>3)&1), half=k&1
// B: col-permuted (perm16); value(j,k) -> grp=(j>>4)*2+(p>>3), col=p&7,
//               pair=k>>5, word=((k>>4)&1)*2+((k>>3)&1), lane=col*4+((k&7)>>1)
__device__ float g_xs[NROWS];
__device__ float g_ys[NROWS];
__device__ __align__(16) __half g_Af[NROWS * D];
__device__ __align__(16) __half g_Bf[NROWS * D];

// ---------------- prep: fp16 round + fragment scatter + norms ----------------
__device__ __forceinline__ int idxA_h(int r, int k) {
    int grp  = r >> 4;
    int chnk = k >> 4;
    int lane = (r & 7) * 4 + ((k & 7) >> 1);
    int reg  = ((r >> 3) & 1) + 2 * ((k >> 3) & 1);
    return ((((grp * 4 + chnk) * 32) + lane) * 4 + reg) * 2 + (k & 1);
}
__device__ __forceinline__ int idxB_h(int j, int k) {
    int w    = j & 15;                                      // within 16-col block
    int p    = 2 * (w >> 2) + (w & 1) + 8 * ((w >> 1) & 1); // inverse perm16
    int grp  = (j >> 4) * 2 + (p >> 3);
    int col  = p & 7;
    int pair = k >> 5;
    int word = ((k >> 4) & 1) * 2 + ((k >> 3) & 1);
    int lane = col * 4 + ((k & 7) >> 1);
    return ((((grp * 2 + pair) * 32) + lane) * 4 + word) * 2 + (k & 1);
}

__global__ void __launch_bounds__(256)
prep_kernel(const float* __restrict__ A, const float* __restrict__ B,
            int rows_each) {
    int half = gridDim.x >> 1;
    int bid  = blockIdx.x;
    bool isB = bid >= half;
    if (isB) bid -= half;

    int w    = bid * 8 + (threadIdx.x >> 5);
    int lane = threadIdx.x & 31;
    if (w >= rows_each) return;
    const float* r = (isB ? B : A) + (size_t)w * D;
    float f0 = r[lane];
    float f1 = r[lane + 32];

    if (!isB) {
        g_Af[idxA_h(w, lane)]      = __float2half_rn(f0);
        g_Af[idxA_h(w, lane + 32)] = __float2half_rn(f1);
    } else {
        g_Bf[idxB_h(w, lane)]      = __float2half_rn(f0);
        g_Bf[idxB_h(w, lane + 32)] = __float2half_rn(f1);
    }

    float s = f0 * f0 + f1 * f1;   // norms from exact f32
#pragma unroll
    for (int o = 16; o; o >>= 1) s += __shfl_xor_sync(0xffffffffu, s, o);
    if (lane == 0) (isB ? g_ys : g_xs)[w] = -GAMMA * s;
}

// ---------------- fp16 mma helper ----------------
__device__ __forceinline__ void mma_f16(float* d, const uint32_t* a,
                                        const uint32_t* b) {
    asm volatile(
        "mma.sync.aligned.m16n8k16.row.col.f32.f16.f16.f32 "
        "{%0,%1,%2,%3}, {%4,%5,%6,%7}, {%8,%9}, {%0,%1,%2,%3};"
        : "+f"(d[0]), "+f"(d[1]), "+f"(d[2]), "+f"(d[3])
        : "r"(a[0]), "r"(a[1]), "r"(a[2]), "r"(a[3]), "r"(b[0]), "r"(b[1]));
}

// ---------------- main: fp16 HMMA, 64x64 warp tile, 2 CTA/SM --------------
__global__ void __launch_bounds__(256, 2)
rbf_f16_kernel(float* __restrict__ out, int N) {
    const int tid  = threadIdx.x;
    const int lane = tid & 31;
    const int wid  = tid >> 5;
    const int gID  = lane >> 2;
    const int tig  = lane & 3;
    const int wm   = wid >> 2;    // 0..1 : 64-row slab
    const int wn   = wid & 3;     // 0..3 : 64-col slab
    const int row0 = blockIdx.y * BM;
    const int col0 = blockIdx.x * BN;

    const uint4* Af = reinterpret_cast<const uint4*>(g_Af);
    const uint4* Bf = reinterpret_cast<const uint4*>(g_Bf);

    // ---- hoist ALL B fragments for this warp's 64-col slab (16 LDG.128) ----
    uint4 bf[16];   // [group(8 cols)][chunk-pair(32 k)]
    {
        const int bgrp0 = (col0 >> 3) + wn * 8;
#pragma unroll
        for (int g = 0; g < 8; g++)
#pragma unroll
            for (int p = 0; p < 2; p++)
                bf[g * 2 + p] = Bf[(size_t)(((bgrp0 + g) * 2 + p) * 32 + lane)];
    }
    const uint32_t* bw = reinterpret_cast<const uint32_t*>(bf);

#pragma unroll
    for (int mt = 0; mt < 4; mt++) {
        // A fragments for this 16-row group (4 LDG.128)
        uint4 af[4];
        const int agrp = (row0 >> 4) + wm * 4 + mt;
#pragma unroll
        for (int c = 0; c < 4; c++)
            af[c] = Af[(size_t)((agrp * 4 + c) * 32 + lane)];
        const uint32_t* aw = reinterpret_cast<const uint32_t*>(af);

        const int rbase = row0 + wm * 64 + mt * 16 + gID;
        const float xs0 = g_xs[rbase];
        const float xs1 = g_xs[rbase + 8];

#pragma unroll
        for (int pr = 0; pr < 4; pr++) {
            float accE[4] = {0.f, 0.f, 0.f, 0.f};
            float accO[4] = {0.f, 0.f, 0.f, 0.f};
#pragma unroll
            for (int c = 0; c < 4; c++) {   // 4 k-chunks of 16
                const uint32_t* a  = aw + c * 4;
                const uint32_t* bE =
                    bw + ((2 * pr) * 2 + (c >> 1)) * 4 + (c & 1) * 2;
                const uint32_t* bO =
                    bw + ((2 * pr + 1) * 2 + (c >> 1)) * 4 + (c & 1) * 2;
                mma_f16(accE, a, bE);
                mma_f16(accO, a, bO);
            }
            const int c = col0 + wn * 64 + pr * 16 + 4 * tig;
            const float4 ys4 = *reinterpret_cast<const float4*>(&g_ys[c]);
            float4 v0, v1;
            v0.x = __expf(fminf(xs0 + ys4.x + TWOG * accE[0], 0.f));
            v0.y = __expf(fminf(xs0 + ys4.y + TWOG * accE[1], 0.f));
            v0.z = __expf(fminf(xs0 + ys4.z + TWOG * accO[0], 0.f));
            v0.w = __expf(fminf(xs0 + ys4.w + TWOG * accO[1], 0.f));
            v1.x = __expf(fminf(xs1 + ys4.x + TWOG * accE[2], 0.f));
            v1.y = __expf(fminf(xs1 + ys4.y + TWOG * accE[3], 0.f));
            v1.z = __expf(fminf(xs1 + ys4.z + TWOG * accO[2], 0.f));
            v1.w = __expf(fminf(xs1 + ys4.w + TWOG * accO[3], 0.f));
            __stcs(reinterpret_cast<float4*>(out + (size_t)rbase * N + c), v0);
            __stcs(reinterpret_cast<float4*>(out + (size_t)(rbase + 8) * N + c), v1);
        }
    }
}

// ---------------------------------------------------------------------------
extern "C" void kernel_launch(void* const* d_in, const int* in_sizes, int n_in,
                              void* d_out, int out_size) {
    const float* A = (const float*)d_in[0];  // data        [M, 64]
    const float* B = (const float*)d_in[1];  // support_vec [N, 64]
    float* out     = (float*)d_out;          // [M, N]

    const int M = in_sizes[0] / D;           // 8192
    const int N = in_sizes[1] / D;           // 8192

    prep_kernel<<<(M + 7) / 8 * 2, 256>>>(A, B, M);

    dim3 grid(N / BN, M / BM);
    rbf_f16_kernel<<<grid, 256>>>(out, N);
}

// round 9
// speedup vs baseline: 1.6237x; 1.0045x over previous
#include <cuda_runtime.h>
#include <cuda_fp16.h>
#include <cstdint>

#define D      64
#define NROWS  8192
#define BM     128
#define BN     256
#define GAMMA  0.015625f
#define LOG2E  1.4426950408889634f
#define TWOGL  (0.03125f * LOG2E)

// ---------------- device scratch: fp16 fragment-layout inputs ----------------
// A (m16n8k16): value(r,k) -> grp=r>>4, chunk=k>>4, lane=(r&7)*4+((k&7)>>1),
//               reg=((r>>3)&1)+2*((k>>3)&1), half=k&1
// B: col-permuted (perm16); value(j,k) -> grp=(j>>4)*2+(p>>3), col=p&7,
//               pair=k>>5, word=((k>>4)&1)*2+((k>>3)&1), lane=col*4+((k&7)>>1)
__device__ float g_xs[NROWS];   // -gamma*log2e*||x||^2
__device__ float g_ys[NROWS];
__device__ __align__(16) __half g_Af[NROWS * D];
__device__ __align__(16) __half g_Bf[NROWS * D];

// ---------------- prep: half2-paired fragment scatter + scaled norms --------
__global__ void __launch_bounds__(256)
prep_kernel(const float* __restrict__ A, const float* __restrict__ B,
            int rows_each) {
    int half = gridDim.x >> 1;
    int bid  = blockIdx.x;
    bool isB = bid >= half;
    if (isB) bid -= half;

    int w    = bid * 8 + (threadIdx.x >> 5);
    int lane = threadIdx.x & 31;       // handles k = 2*lane, 2*lane+1
    if (w >= rows_each) return;

    float2 f = reinterpret_cast<const float2*>((isB ? B : A) + (size_t)w * D)[lane];
    __half2 h = __floats2half2_rn(f.x, f.y);

    if (!isB) {
        int grp  = w >> 4;
        int chnk = lane >> 3;
        int ln   = (w & 7) * 4 + (lane & 3);
        int reg  = ((w >> 3) & 1) + 2 * ((lane >> 2) & 1);
        reinterpret_cast<__half2*>(g_Af)[((grp * 4 + chnk) * 32 + ln) * 4 + reg] = h;
    } else {
        int w16  = w & 15;
        int p    = 2 * (w16 >> 2) + (w16 & 1) + 8 * ((w16 >> 1) & 1); // inv perm16
        int grp  = (w >> 4) * 2 + (p >> 3);
        int ln   = (p & 7) * 4 + (lane & 3);
        int pair = lane >> 4;
        int wrd  = ((lane >> 3) & 1) * 2 + ((lane >> 2) & 1);
        reinterpret_cast<__half2*>(g_Bf)[((grp * 2 + pair) * 32 + ln) * 4 + wrd] = h;
    }

    float s = f.x * f.x + f.y * f.y;   // norms from exact f32
#pragma unroll
    for (int o = 16; o; o >>= 1) s += __shfl_xor_sync(0xffffffffu, s, o);
    if (lane == 0) (isB ? g_ys : g_xs)[w] = -(GAMMA * LOG2E) * s;
}

// ---------------- fp16 mma / ex2 helpers ----------------
__device__ __forceinline__ void mma_f16(float* d, const uint32_t* a,
                                        const uint32_t* b) {
    asm volatile(
        "mma.sync.aligned.m16n8k16.row.col.f32.f16.f16.f32 "
        "{%0,%1,%2,%3}, {%4,%5,%6,%7}, {%8,%9}, {%0,%1,%2,%3};"
        : "+f"(d[0]), "+f"(d[1]), "+f"(d[2]), "+f"(d[3])
        : "r"(a[0]), "r"(a[1]), "r"(a[2]), "r"(a[3]), "r"(b[0]), "r"(b[1]));
}
__device__ __forceinline__ float ex2(float x) {
    float r;
    asm("ex2.approx.f32 %0, %1;" : "=f"(r) : "f"(x));
    return r;
}
__device__ __forceinline__ float epi(float acc, float xy) {
    return ex2(fminf(fmaf(TWOGL, acc, xy), 0.f));
}

// ---------------- main: fp16 HMMA, 64x64 warp tile, 2 CTA/SM --------------
__global__ void __launch_bounds__(256, 2)
rbf_f16_kernel(float* __restrict__ out, int N) {
    const int tid  = threadIdx.x;
    const int lane = tid & 31;
    const int wid  = tid >> 5;
    const int gID  = lane >> 2;
    const int tig  = lane & 3;
    const int wm   = wid >> 2;    // 0..1 : 64-row slab
    const int wn   = wid & 3;     // 0..3 : 64-col slab
    const int row0 = blockIdx.y * BM;
    const int col0 = blockIdx.x * BN;

    const uint4* Af = reinterpret_cast<const uint4*>(g_Af);
    const uint4* Bf = reinterpret_cast<const uint4*>(g_Bf);

    // ---- hoist ALL B fragments for this warp's 64-col slab (16 LDG.128) ----
    uint4 bf[16];   // [group(8 cols)][chunk-pair(32 k)]
    {
        const int bgrp0 = (col0 >> 3) + wn * 8;
#pragma unroll
        for (int g = 0; g < 8; g++)
#pragma unroll
            for (int p = 0; p < 2; p++)
                bf[g * 2 + p] = Bf[(size_t)(((bgrp0 + g) * 2 + p) * 32 + lane)];
    }
    const uint32_t* bw = reinterpret_cast<const uint32_t*>(bf);

#pragma unroll
    for (int mt = 0; mt < 4; mt++) {
        // A fragments for this 16-row group (4 LDG.128)
        uint4 af[4];
        const int agrp = (row0 >> 4) + wm * 4 + mt;
#pragma unroll
        for (int c = 0; c < 4; c++)
            af[c] = Af[(size_t)((agrp * 4 + c) * 32 + lane)];
        const uint32_t* aw = reinterpret_cast<const uint32_t*>(af);

        const int rbase = row0 + wm * 64 + mt * 16 + gID;
        const float xs0 = g_xs[rbase];
        const float xs1 = g_xs[rbase + 8];

#pragma unroll
        for (int pr = 0; pr < 4; pr++) {
            float accE[4] = {0.f, 0.f, 0.f, 0.f};
            float accO[4] = {0.f, 0.f, 0.f, 0.f};
#pragma unroll
            for (int c = 0; c < 4; c++) {   // 4 k-chunks of 16
                const uint32_t* a  = aw + c * 4;
                const uint32_t* bE =
                    bw + ((2 * pr) * 2 + (c >> 1)) * 4 + (c & 1) * 2;
                const uint32_t* bO =
                    bw + ((2 * pr + 1) * 2 + (c >> 1)) * 4 + (c & 1) * 2;
                mma_f16(accE, a, bE);
                mma_f16(accO, a, bO);
            }
            const int c = col0 + wn * 64 + pr * 16 + 4 * tig;
            const float4 ys4 = *reinterpret_cast<const float4*>(&g_ys[c]);
            float4 v0, v1;
            v0.x = epi(accE[0], xs0 + ys4.x);
            v0.y = epi(accE[1], xs0 + ys4.y);
            v0.z = epi(accO[0], xs0 + ys4.z);
            v0.w = epi(accO[1], xs0 + ys4.w);
            v1.x = epi(accE[2], xs1 + ys4.x);
            v1.y = epi(accE[3], xs1 + ys4.y);
            v1.z = epi(accO[2], xs1 + ys4.z);
            v1.w = epi(accO[3], xs1 + ys4.w);
            __stcs(reinterpret_cast<float4*>(out + (size_t)rbase * N + c), v0);
            __stcs(reinterpret_cast<float4*>(out + (size_t)(rbase + 8) * N + c), v1);
        }
    }
}

// ---------------------------------------------------------------------------
extern "C" void kernel_launch(void* const* d_in, const int* in_sizes, int n_in,
                              void* d_out, int out_size) {
    const float* A = (const float*)d_in[0];  // data        [M, 64]
    const float* B = (const float*)d_in[1];  // support_vec [N, 64]
    float* out     = (float*)d_out;          // [M, N]

    const int M = in_sizes[0] / D;           // 8192
    const int N = in_sizes[1] / D;           // 8192

    prep_kernel<<<(M + 7) / 8 * 2, 256>>>(A, B, M);

    dim3 grid(N / BN, M / BM);
    rbf_f16_kernel<<<grid, 256>>>(out, N);
}